// round 15
// baseline (speedup 1.0000x reference)
#include <cuda_runtime.h>
#include <cuda_bf16.h>

#define NODES_CAP 100000
#define EDGES_CAP 1600000
#define CH 64

// Scratch
__device__ float g_agg[(size_t)NODES_CAP * CH];   // fallback path only
__device__ int g_counts[NODES_CAP];
__device__ int g_offsets[NODES_CAP];
__device__ int g_cursor[NODES_CAP];
__device__ int g_sorted_src[EDGES_CAP];
__device__ int g_partials[256];
__device__ int g_ei_is64;

// ---------------------------------------------------------------------------
// Probe edge_index dtype (int64 values < 2^31 have zero odd 32-bit words).
// ---------------------------------------------------------------------------
__global__ void probe_ei_kernel(const int* __restrict__ ei32) {
    int all_zero = 1;
    for (int i = 1; i < 64; i += 2)
        if (ei32[i] != 0) { all_zero = 0; break; }
    g_ei_is64 = all_zero;
}

__device__ __forceinline__ void load_edge(const void* ei_raw, int E, int e,
                                          int& s, int& d) {
    if (g_ei_is64) {
        const long long* ei = (const long long*)ei_raw;
        s = (int)ei[e];
        d = (int)ei[(size_t)E + e];
    } else {
        const int* ei = (const int*)ei_raw;
        s = ei[e];
        d = ei[(size_t)E + e];
    }
}

__device__ __forceinline__ int load_dst(const void* ei_raw, int E, int e) {
    if (g_ei_is64) return (int)((const long long*)ei_raw)[(size_t)E + e];
    return ((const int*)ei_raw)[(size_t)E + e];
}

// ---------------------------------------------------------------------------
// Counting sort by destination (CSR build)
// ---------------------------------------------------------------------------
__global__ void zero_counts_kernel(int* __restrict__ counts, int n) {
    int i = blockIdx.x * blockDim.x + threadIdx.x;
    if (i < n) counts[i] = 0;
}

__global__ void hist_kernel(const void* __restrict__ ei_raw,
                            int* __restrict__ counts, int E, int n) {
    int e = blockIdx.x * blockDim.x + threadIdx.x;
    if (e >= E) return;
    int d = load_dst(ei_raw, E, e);
    if ((unsigned)d >= (unsigned)n) return;
    atomicAdd(&counts[d], 1);
}

__global__ void scan1_kernel(const int* __restrict__ counts,
                             int* __restrict__ offsets,
                             int* __restrict__ partials, int n) {
    __shared__ int sh[1024];
    int i = blockIdx.x * 1024 + threadIdx.x;
    int c = (i < n) ? counts[i] : 0;
    sh[threadIdx.x] = c;
    __syncthreads();
    for (int off = 1; off < 1024; off <<= 1) {
        int t = (threadIdx.x >= off) ? sh[threadIdx.x - off] : 0;
        __syncthreads();
        sh[threadIdx.x] += t;
        __syncthreads();
    }
    if (i < n) offsets[i] = sh[threadIdx.x] - c;
    if (threadIdx.x == 1023) partials[blockIdx.x] = sh[1023];
}

__global__ void scan2_kernel(int* __restrict__ partials, int nb) {
    __shared__ int sh[256];
    int i = threadIdx.x;
    int v = (i < nb) ? partials[i] : 0;
    sh[i] = v;
    __syncthreads();
    for (int off = 1; off < 256; off <<= 1) {
        int t = (i >= off) ? sh[i - off] : 0;
        __syncthreads();
        sh[i] += t;
        __syncthreads();
    }
    if (i < nb) partials[i] = sh[i] - v;
}

__global__ void scan3_kernel(int* __restrict__ offsets,
                             const int* __restrict__ partials,
                             int* __restrict__ cursor, int n) {
    int i = blockIdx.x * blockDim.x + threadIdx.x;
    if (i < n) {
        int o = offsets[i] + partials[i >> 10];
        offsets[i] = o;
        cursor[i] = o;
    }
}

__global__ void fill_kernel(const void* __restrict__ ei_raw,
                            int* __restrict__ cursor,
                            int* __restrict__ sorted_src, int E, int n) {
    int e = blockIdx.x * blockDim.x + threadIdx.x;
    if (e >= E) return;
    int s, d; load_edge(ei_raw, E, e, s, d);
    if ((unsigned)s >= (unsigned)n || (unsigned)d >= (unsigned)n) return;
    int pos = atomicAdd(&cursor[d], 1);
    if (pos < EDGES_CAP) sorted_src[pos] = s;
}

// ---------------------------------------------------------------------------
// Fallback (shapes beyond caps): atomic scatter into g_agg
// ---------------------------------------------------------------------------
__global__ void init_agg_kernel(const float4* __restrict__ x, float4* __restrict__ agg,
                                int n4) {
    int i = blockIdx.x * blockDim.x + threadIdx.x;
    if (i < n4) agg[i] = x[i];
}

__device__ __forceinline__ void red_add_v4(float* p, float4 v) {
    asm volatile("red.global.add.v4.f32 [%0], {%1, %2, %3, %4};"
                 :: "l"(p), "f"(v.x), "f"(v.y), "f"(v.z), "f"(v.w)
                 : "memory");
}

__global__ void scatter_kernel(const float* __restrict__ x,
                               const void* __restrict__ ei_raw,
                               float* __restrict__ agg, int E, int n) {
    int t = blockIdx.x * blockDim.x + threadIdx.x;
    int e = t >> 2;
    if (e >= E) return;
    int sub = t & 3;
    int s, d; load_edge(ei_raw, E, e, s, d);
    if ((unsigned)s >= (unsigned)n || (unsigned)d >= (unsigned)n) return;
    const float4* src = (const float4*)(x + (size_t)s * CH + sub * 16);
    float*        dst = agg + (size_t)d * CH + sub * 16;
    float4 v0 = src[0], v1 = src[1], v2 = src[2], v3 = src[3];
    red_add_v4(dst + 0,  v0);
    red_add_v4(dst + 4,  v1);
    red_add_v4(dst + 8,  v2);
    red_add_v4(dst + 12, v3);
}

// ---------------------------------------------------------------------------
// Fused gather + MLP. Block = 128 threads, 128 nodes.
// SINGLE shared weight buffer (W1 then W2 reloaded in the layer-1->2 sync
// window): smem 66KB->50KB => 4 blocks/SM instead of 3 (16 warps/SM).
// Gather: warp handles 2 nodes concurrently (half-warp x float4 = 256B row
// per edge), 4-unrolled with 4 independent accumulator chains.
// MLP: R7 register tiling (rows {tx,tx+32,tx+64,tx+96} x 16 cols).
// ---------------------------------------------------------------------------
#define MLP_ROWS 128
#define HP 65

__global__ void __launch_bounds__(128)
mlp_kernel(const float* __restrict__ x,
           const float* __restrict__ h_in,          // fallback: g_agg
           const int* __restrict__ offs, const int* __restrict__ cnts,
           const int* __restrict__ srt,
           const float* __restrict__ W1, const float* __restrict__ b1,
           const float* __restrict__ W2, const float* __restrict__ b2,
           const float* __restrict__ alpha,
           float* __restrict__ out, int n, int out_size, int use_gather) {
    extern __shared__ float sm[];
    float* Ws  = sm;                  // [64][64] shared by W1 then W2
    float* b1s = Ws + CH * CH;
    float* b2s = b1s + CH;
    float* hs  = b2s + CH;            // [128][65]

    const int tid = threadIdx.x;
    const int tx  = tid & 31;
    const int ty  = tid >> 5;
    const int c0  = ty * 16;
    const int row0 = blockIdx.x * MLP_ROWS;

    for (int i = tid; i < CH * CH; i += 128) Ws[i] = W1[i];
    if (tid < CH) { b1s[tid] = b1[tid]; b2s[tid] = b2[tid]; }

    if (use_gather) {
        const float4* xp = (const float4*)x;   // 16 float4 per row
        const int half = tx >> 4;              // which node of the pair
        const int sub  = tx & 15;              // float4 slot within row
        for (int it = 0; it < 16; it++) {
            int nb = ty * 32 + it * 2 + half;
            int g  = row0 + nb;
            float4 a0 = make_float4(0.f, 0.f, 0.f, 0.f);
            float4 a1 = a0, a2 = a0, a3 = a0;
            if (g < n) {
                a0 = xp[(size_t)g * 16 + sub];          // self (eps=0 GIN)
                int start = offs[g];
                int deg   = cnts[g];
                int j = 0;
                for (; j + 4 <= deg; j += 4) {
                    int s0 = __ldg(srt + start + j);
                    int s1 = __ldg(srt + start + j + 1);
                    int s2 = __ldg(srt + start + j + 2);
                    int s3 = __ldg(srt + start + j + 3);
                    float4 v0 = xp[(size_t)s0 * 16 + sub];
                    float4 v1 = xp[(size_t)s1 * 16 + sub];
                    float4 v2 = xp[(size_t)s2 * 16 + sub];
                    float4 v3 = xp[(size_t)s3 * 16 + sub];
                    a0.x += v0.x; a0.y += v0.y; a0.z += v0.z; a0.w += v0.w;
                    a1.x += v1.x; a1.y += v1.y; a1.z += v1.z; a1.w += v1.w;
                    a2.x += v2.x; a2.y += v2.y; a2.z += v2.z; a2.w += v2.w;
                    a3.x += v3.x; a3.y += v3.y; a3.z += v3.z; a3.w += v3.w;
                }
                for (; j < deg; j++) {
                    int s0 = __ldg(srt + start + j);
                    float4 v0 = xp[(size_t)s0 * 16 + sub];
                    a0.x += v0.x; a0.y += v0.y; a0.z += v0.z; a0.w += v0.w;
                }
            }
            float* dp = hs + nb * HP + sub * 4;
            dp[0] = (a0.x + a1.x) + (a2.x + a3.x);
            dp[1] = (a0.y + a1.y) + (a2.y + a3.y);
            dp[2] = (a0.z + a1.z) + (a2.z + a3.z);
            dp[3] = (a0.w + a1.w) + (a2.w + a3.w);
        }
    } else {
        const float4* src = (const float4*)(h_in + (size_t)row0 * CH);
        int valid4 = (n - row0 < MLP_ROWS ? (n - row0 > 0 ? n - row0 : 0) : MLP_ROWS) * (CH / 4);
        for (int i = tid; i < MLP_ROWS * (CH / 4); i += 128) {
            float4 v = (i < valid4) ? src[i] : make_float4(0.f, 0.f, 0.f, 0.f);
            int r = i >> 4, q = (i & 15) * 4;
            float* dp = hs + r * HP + q;
            dp[0] = v.x; dp[1] = v.y; dp[2] = v.z; dp[3] = v.w;
        }
    }
    __syncthreads();

    const float gate = 1.0f / (1.0f + __expf(-alpha[0]));

    float acc[4][16];

    // ---- Layer 1: relu(h @ W1 + b1) ----
    #pragma unroll
    for (int j = 0; j < 4; j++)
        #pragma unroll
        for (int c = 0; c < 16; c++) acc[j][c] = b1s[c0 + c];

    #pragma unroll 4
    for (int k = 0; k < CH; k++) {
        float hv0 = hs[(tx +  0) * HP + k];
        float hv1 = hs[(tx + 32) * HP + k];
        float hv2 = hs[(tx + 64) * HP + k];
        float hv3 = hs[(tx + 96) * HP + k];
        const float4* wr = (const float4*)(Ws + k * CH + c0);
        float4 wa = wr[0], wb = wr[1], wc = wr[2], wd = wr[3];
        float w[16] = {wa.x, wa.y, wa.z, wa.w, wb.x, wb.y, wb.z, wb.w,
                       wc.x, wc.y, wc.z, wc.w, wd.x, wd.y, wd.z, wd.w};
        #pragma unroll
        for (int c = 0; c < 16; c++) {
            acc[0][c] += hv0 * w[c];
            acc[1][c] += hv1 * w[c];
            acc[2][c] += hv2 * w[c];
            acc[3][c] += hv3 * w[c];
        }
    }
    __syncthreads();   // done reading Ws (W1) and hs
    // Write relu(h1) and reload W2 into the same weight buffer.
    #pragma unroll
    for (int j = 0; j < 4; j++)
        #pragma unroll
        for (int c = 0; c < 16; c++)
            hs[(32 * j + tx) * HP + c0 + c] = fmaxf(acc[j][c], 0.f);
    for (int i = tid; i < CH * CH; i += 128) Ws[i] = W2[i];
    __syncthreads();

    // ---- Layer 2: gate * (h1 @ W2 + b2) ----
    #pragma unroll
    for (int j = 0; j < 4; j++)
        #pragma unroll
        for (int c = 0; c < 16; c++) acc[j][c] = b2s[c0 + c];

    #pragma unroll 4
    for (int k = 0; k < CH; k++) {
        float hv0 = hs[(tx +  0) * HP + k];
        float hv1 = hs[(tx + 32) * HP + k];
        float hv2 = hs[(tx + 64) * HP + k];
        float hv3 = hs[(tx + 96) * HP + k];
        const float4* wr = (const float4*)(Ws + k * CH + c0);
        float4 wa = wr[0], wb = wr[1], wc = wr[2], wd = wr[3];
        float w[16] = {wa.x, wa.y, wa.z, wa.w, wb.x, wb.y, wb.z, wb.w,
                       wc.x, wc.y, wc.z, wc.w, wd.x, wd.y, wd.z, wd.w};
        #pragma unroll
        for (int c = 0; c < 16; c++) {
            acc[0][c] += hv0 * w[c];
            acc[1][c] += hv1 * w[c];
            acc[2][c] += hv2 * w[c];
            acc[3][c] += hv3 * w[c];
        }
    }
    __syncthreads();
    #pragma unroll
    for (int j = 0; j < 4; j++)
        #pragma unroll
        for (int c = 0; c < 16; c++)
            hs[(32 * j + tx) * HP + c0 + c] = gate * acc[j][c];
    __syncthreads();

    {
        int validf = (n - row0 < MLP_ROWS ? (n - row0 > 0 ? n - row0 : 0) : MLP_ROWS) * CH;
        float* dst = out + (size_t)row0 * CH;
        for (int i = tid; i < MLP_ROWS * CH; i += 128) {
            if (i < validf) {
                int r = i >> 6, c = i & 63;
                dst[i] = hs[r * HP + c];
            }
        }
    }

    if (blockIdx.x == 0 && tid == 0 && out_size > n * CH) out[(size_t)n * CH] = gate;
}

// ---------------------------------------------------------------------------
extern "C" void kernel_launch(void* const* d_in, const int* in_sizes, int n_in,
                              void* d_out, int out_size) {
    const float* x     = (const float*)d_in[0];
    const void*  ei    = d_in[1];
    const float* W1    = (const float*)d_in[2];
    const float* b1    = (const float*)d_in[3];
    const float* W2    = (const float*)d_in[4];
    const float* b2    = (const float*)d_in[5];
    const float* alpha = (const float*)d_in[6];
    float* out = (float*)d_out;

    int n = in_sizes[0] / CH;
    int E = in_sizes[1] / 2;

    float *agg; int *counts, *offsets, *cursor, *sorted, *partials;
    cudaGetSymbolAddress((void**)&agg,      g_agg);
    cudaGetSymbolAddress((void**)&counts,   g_counts);
    cudaGetSymbolAddress((void**)&offsets,  g_offsets);
    cudaGetSymbolAddress((void**)&cursor,   g_cursor);
    cudaGetSymbolAddress((void**)&sorted,   g_sorted_src);
    cudaGetSymbolAddress((void**)&partials, g_partials);

    probe_ei_kernel<<<1, 1>>>((const int*)ei);

    int smem = (CH * CH + 2 * CH + MLP_ROWS * HP) * sizeof(float);
    cudaFuncSetAttribute(mlp_kernel, cudaFuncAttributeMaxDynamicSharedMemorySize, smem);

    bool sortable = (n <= NODES_CAP) && (E <= EDGES_CAP) && (((n + 1023) / 1024) <= 256);
    int ncap = n < NODES_CAP ? n : NODES_CAP;
    int mblocks = (ncap + MLP_ROWS - 1) / MLP_ROWS;

    if (sortable) {
        int nb = (n + 1023) / 1024;
        zero_counts_kernel<<<(n + 255) / 256, 256>>>(counts, n);
        hist_kernel<<<(E + 255) / 256, 256>>>(ei, counts, E, n);
        scan1_kernel<<<nb, 1024>>>(counts, offsets, partials, n);
        scan2_kernel<<<1, 256>>>(partials, nb);
        scan3_kernel<<<(n + 255) / 256, 256>>>(offsets, partials, cursor, n);
        fill_kernel<<<(E + 255) / 256, 256>>>(ei, cursor, sorted, E, n);
        mlp_kernel<<<mblocks, 128, smem>>>(x, x, offsets, counts, sorted,
                                           W1, b1, W2, b2, alpha, out, n, out_size, 1);
    } else {
        int n4 = ncap * (CH / 4);
        init_agg_kernel<<<(n4 + 255) / 256, 256>>>((const float4*)x, (float4*)agg, n4);
        long long thr = (long long)E * 4;
        scatter_kernel<<<(int)((thr + 255) / 256), 256>>>(x, ei, agg, E, ncap);
        mlp_kernel<<<mblocks, 128, smem>>>(x, agg, offsets, counts, sorted,
                                           W1, b1, W2, b2, alpha, out, ncap, out_size, 0);
    }
}

// round 16
// speedup vs baseline: 1.0818x; 1.0818x over previous
#include <cuda_runtime.h>
#include <cuda_bf16.h>

#define NODES_CAP 100000
#define EDGES_CAP 1600000
#define CH 64

// Scratch
__device__ float g_agg[(size_t)NODES_CAP * CH];   // fallback path only
__device__ int g_counts[NODES_CAP];
__device__ int g_offsets[NODES_CAP];
__device__ int g_cursor[NODES_CAP];
__device__ int g_sorted_src[EDGES_CAP];
__device__ int g_partials[256];
__device__ int g_ei_is64;

// ---------------------------------------------------------------------------
// Probe edge_index dtype (int64 values < 2^31 have zero odd 32-bit words).
// ---------------------------------------------------------------------------
__global__ void probe_ei_kernel(const int* __restrict__ ei32) {
    int all_zero = 1;
    for (int i = 1; i < 64; i += 2)
        if (ei32[i] != 0) { all_zero = 0; break; }
    g_ei_is64 = all_zero;
}

__device__ __forceinline__ void load_edge(const void* ei_raw, int E, int e,
                                          int& s, int& d) {
    if (g_ei_is64) {
        const long long* ei = (const long long*)ei_raw;
        s = (int)ei[e];
        d = (int)ei[(size_t)E + e];
    } else {
        const int* ei = (const int*)ei_raw;
        s = ei[e];
        d = ei[(size_t)E + e];
    }
}

__device__ __forceinline__ int load_dst(const void* ei_raw, int E, int e) {
    if (g_ei_is64) return (int)((const long long*)ei_raw)[(size_t)E + e];
    return ((const int*)ei_raw)[(size_t)E + e];
}

// ---------------------------------------------------------------------------
// Counting sort by destination (CSR build)
// ---------------------------------------------------------------------------
__global__ void zero_counts_kernel(int* __restrict__ counts, int n) {
    int i = blockIdx.x * blockDim.x + threadIdx.x;
    if (i < n) counts[i] = 0;
}

__global__ void hist_kernel(const void* __restrict__ ei_raw,
                            int* __restrict__ counts, int E, int n) {
    int e = blockIdx.x * blockDim.x + threadIdx.x;
    if (e >= E) return;
    int d = load_dst(ei_raw, E, e);
    if ((unsigned)d >= (unsigned)n) return;
    atomicAdd(&counts[d], 1);
}

__global__ void scan1_kernel(const int* __restrict__ counts,
                             int* __restrict__ offsets,
                             int* __restrict__ partials, int n) {
    __shared__ int sh[1024];
    int i = blockIdx.x * 1024 + threadIdx.x;
    int c = (i < n) ? counts[i] : 0;
    sh[threadIdx.x] = c;
    __syncthreads();
    for (int off = 1; off < 1024; off <<= 1) {
        int t = (threadIdx.x >= off) ? sh[threadIdx.x - off] : 0;
        __syncthreads();
        sh[threadIdx.x] += t;
        __syncthreads();
    }
    if (i < n) offsets[i] = sh[threadIdx.x] - c;
    if (threadIdx.x == 1023) partials[blockIdx.x] = sh[1023];
}

__global__ void scan2_kernel(int* __restrict__ partials, int nb) {
    __shared__ int sh[256];
    int i = threadIdx.x;
    int v = (i < nb) ? partials[i] : 0;
    sh[i] = v;
    __syncthreads();
    for (int off = 1; off < 256; off <<= 1) {
        int t = (i >= off) ? sh[i - off] : 0;
        __syncthreads();
        sh[i] += t;
        __syncthreads();
    }
    if (i < nb) partials[i] = sh[i] - v;
}

__global__ void scan3_kernel(int* __restrict__ offsets,
                             const int* __restrict__ partials,
                             int* __restrict__ cursor, int n) {
    int i = blockIdx.x * blockDim.x + threadIdx.x;
    if (i < n) {
        int o = offsets[i] + partials[i >> 10];
        offsets[i] = o;
        cursor[i] = o;
    }
}

__global__ void fill_kernel(const void* __restrict__ ei_raw,
                            int* __restrict__ cursor,
                            int* __restrict__ sorted_src, int E, int n) {
    int e = blockIdx.x * blockDim.x + threadIdx.x;
    if (e >= E) return;
    int s, d; load_edge(ei_raw, E, e, s, d);
    if ((unsigned)s >= (unsigned)n || (unsigned)d >= (unsigned)n) return;
    int pos = atomicAdd(&cursor[d], 1);
    if (pos < EDGES_CAP) sorted_src[pos] = s;
}

// ---------------------------------------------------------------------------
// Fallback (shapes beyond caps): atomic scatter into g_agg
// ---------------------------------------------------------------------------
__global__ void init_agg_kernel(const float4* __restrict__ x, float4* __restrict__ agg,
                                int n4) {
    int i = blockIdx.x * blockDim.x + threadIdx.x;
    if (i < n4) agg[i] = x[i];
}

__device__ __forceinline__ void red_add_v4(float* p, float4 v) {
    asm volatile("red.global.add.v4.f32 [%0], {%1, %2, %3, %4};"
                 :: "l"(p), "f"(v.x), "f"(v.y), "f"(v.z), "f"(v.w)
                 : "memory");
}

__global__ void scatter_kernel(const float* __restrict__ x,
                               const void* __restrict__ ei_raw,
                               float* __restrict__ agg, int E, int n) {
    int t = blockIdx.x * blockDim.x + threadIdx.x;
    int e = t >> 2;
    if (e >= E) return;
    int sub = t & 3;
    int s, d; load_edge(ei_raw, E, e, s, d);
    if ((unsigned)s >= (unsigned)n || (unsigned)d >= (unsigned)n) return;
    const float4* src = (const float4*)(x + (size_t)s * CH + sub * 16);
    float*        dst = agg + (size_t)d * CH + sub * 16;
    float4 v0 = src[0], v1 = src[1], v2 = src[2], v3 = src[3];
    red_add_v4(dst + 0,  v0);
    red_add_v4(dst + 4,  v1);
    red_add_v4(dst + 8,  v2);
    red_add_v4(dst + 12, v3);
}

// ---------------------------------------------------------------------------
// Fused gather + MLP (R13 config: two weight buffers, 66KB smem).
// Gather improvements this round:
//  - CSR offsets/counts preloaded once per warp, distributed via __shfl_sync
//    (removes 2 dependent L2 loads from every pair-step's critical path).
//  - Edge-index prefetch software pipeline: next 4 srt indices issued in the
//    same window as the current 4 row loads -> one L2 latency per 4 edges.
// ---------------------------------------------------------------------------
#define MLP_ROWS 128
#define HP 65

__global__ void __launch_bounds__(128)
mlp_kernel(const float* __restrict__ x,
           const float* __restrict__ h_in,          // fallback: g_agg
           const int* __restrict__ offs, const int* __restrict__ cnts,
           const int* __restrict__ srt,
           const float* __restrict__ W1, const float* __restrict__ b1,
           const float* __restrict__ W2, const float* __restrict__ b2,
           const float* __restrict__ alpha,
           float* __restrict__ out, int n, int out_size, int use_gather) {
    extern __shared__ float sm[];
    float* W1s = sm;
    float* W2s = W1s + CH * CH;
    float* b1s = W2s + CH * CH;
    float* b2s = b1s + CH;
    float* hs  = b2s + CH;            // [128][65]

    const int tid = threadIdx.x;
    const int tx  = tid & 31;
    const int ty  = tid >> 5;
    const int c0  = ty * 16;
    const int row0 = blockIdx.x * MLP_ROWS;

    for (int i = tid; i < CH * CH; i += 128) { W1s[i] = W1[i]; W2s[i] = W2[i]; }
    if (tid < CH) { b1s[tid] = b1[tid]; b2s[tid] = b2[tid]; }

    if (use_gather) {
        const float4* xp = (const float4*)x;   // 16 float4 per row
        const int half = tx >> 4;              // which node of the pair
        const int sub  = tx & 15;              // float4 slot within row

        // Stage this warp's 32 nodes' CSR metadata in registers (1 coalesced load).
        int myoff = 0, mycnt = 0;
        {
            int gi = row0 + ty * 32 + tx;
            if (gi < n) { myoff = offs[gi]; mycnt = cnts[gi]; }
        }

        for (int it = 0; it < 16; it++) {
            int nodeLane = it * 2 + half;
            int start = __shfl_sync(0xffffffffu, myoff, nodeLane);
            int deg   = __shfl_sync(0xffffffffu, mycnt, nodeLane);
            int nb = ty * 32 + nodeLane;
            int g  = row0 + nb;
            float4 a0 = make_float4(0.f, 0.f, 0.f, 0.f);
            float4 a1 = a0, a2 = a0, a3 = a0;
            if (g < n) {
                a0 = xp[(size_t)g * 16 + sub];          // self (eps=0 GIN)
                int j = 0;
                if (j + 4 <= deg) {
                    // Prologue: first index batch.
                    int s0 = __ldg(srt + start);
                    int s1 = __ldg(srt + start + 1);
                    int s2 = __ldg(srt + start + 2);
                    int s3 = __ldg(srt + start + 3);
                    for (;;) {
                        // Row loads for current batch.
                        float4 v0 = xp[(size_t)s0 * 16 + sub];
                        float4 v1 = xp[(size_t)s1 * 16 + sub];
                        float4 v2 = xp[(size_t)s2 * 16 + sub];
                        float4 v3 = xp[(size_t)s3 * 16 + sub];
                        j += 4;
                        bool more = (j + 4 <= deg);
                        if (more) {
                            // Prefetch next index batch while rows are in flight.
                            s0 = __ldg(srt + start + j);
                            s1 = __ldg(srt + start + j + 1);
                            s2 = __ldg(srt + start + j + 2);
                            s3 = __ldg(srt + start + j + 3);
                        }
                        a0.x += v0.x; a0.y += v0.y; a0.z += v0.z; a0.w += v0.w;
                        a1.x += v1.x; a1.y += v1.y; a1.z += v1.z; a1.w += v1.w;
                        a2.x += v2.x; a2.y += v2.y; a2.z += v2.z; a2.w += v2.w;
                        a3.x += v3.x; a3.y += v3.y; a3.z += v3.z; a3.w += v3.w;
                        if (!more) break;
                    }
                }
                for (; j < deg; j++) {
                    int s0 = __ldg(srt + start + j);
                    float4 v0 = xp[(size_t)s0 * 16 + sub];
                    a0.x += v0.x; a0.y += v0.y; a0.z += v0.z; a0.w += v0.w;
                }
            }
            float* dp = hs + nb * HP + sub * 4;
            dp[0] = (a0.x + a1.x) + (a2.x + a3.x);
            dp[1] = (a0.y + a1.y) + (a2.y + a3.y);
            dp[2] = (a0.z + a1.z) + (a2.z + a3.z);
            dp[3] = (a0.w + a1.w) + (a2.w + a3.w);
        }
    } else {
        const float4* src = (const float4*)(h_in + (size_t)row0 * CH);
        int valid4 = (n - row0 < MLP_ROWS ? (n - row0 > 0 ? n - row0 : 0) : MLP_ROWS) * (CH / 4);
        for (int i = tid; i < MLP_ROWS * (CH / 4); i += 128) {
            float4 v = (i < valid4) ? src[i] : make_float4(0.f, 0.f, 0.f, 0.f);
            int r = i >> 4, q = (i & 15) * 4;
            float* dp = hs + r * HP + q;
            dp[0] = v.x; dp[1] = v.y; dp[2] = v.z; dp[3] = v.w;
        }
    }
    __syncthreads();

    const float gate = 1.0f / (1.0f + __expf(-alpha[0]));

    float acc[4][16];

    // ---- Layer 1: relu(h @ W1 + b1) ----
    #pragma unroll
    for (int j = 0; j < 4; j++)
        #pragma unroll
        for (int c = 0; c < 16; c++) acc[j][c] = b1s[c0 + c];

    #pragma unroll 4
    for (int k = 0; k < CH; k++) {
        float hv0 = hs[(tx +  0) * HP + k];
        float hv1 = hs[(tx + 32) * HP + k];
        float hv2 = hs[(tx + 64) * HP + k];
        float hv3 = hs[(tx + 96) * HP + k];
        const float4* wr = (const float4*)(W1s + k * CH + c0);
        float4 wa = wr[0], wb = wr[1], wc = wr[2], wd = wr[3];
        float w[16] = {wa.x, wa.y, wa.z, wa.w, wb.x, wb.y, wb.z, wb.w,
                       wc.x, wc.y, wc.z, wc.w, wd.x, wd.y, wd.z, wd.w};
        #pragma unroll
        for (int c = 0; c < 16; c++) {
            acc[0][c] += hv0 * w[c];
            acc[1][c] += hv1 * w[c];
            acc[2][c] += hv2 * w[c];
            acc[3][c] += hv3 * w[c];
        }
    }
    __syncthreads();
    #pragma unroll
    for (int j = 0; j < 4; j++)
        #pragma unroll
        for (int c = 0; c < 16; c++)
            hs[(32 * j + tx) * HP + c0 + c] = fmaxf(acc[j][c], 0.f);
    __syncthreads();

    // ---- Layer 2: gate * (h1 @ W2 + b2) ----
    #pragma unroll
    for (int j = 0; j < 4; j++)
        #pragma unroll
        for (int c = 0; c < 16; c++) acc[j][c] = b2s[c0 + c];

    #pragma unroll 4
    for (int k = 0; k < CH; k++) {
        float hv0 = hs[(tx +  0) * HP + k];
        float hv1 = hs[(tx + 32) * HP + k];
        float hv2 = hs[(tx + 64) * HP + k];
        float hv3 = hs[(tx + 96) * HP + k];
        const float4* wr = (const float4*)(W2s + k * CH + c0);
        float4 wa = wr[0], wb = wr[1], wc = wr[2], wd = wr[3];
        float w[16] = {wa.x, wa.y, wa.z, wa.w, wb.x, wb.y, wb.z, wb.w,
                       wc.x, wc.y, wc.z, wc.w, wd.x, wd.y, wd.z, wd.w};
        #pragma unroll
        for (int c = 0; c < 16; c++) {
            acc[0][c] += hv0 * w[c];
            acc[1][c] += hv1 * w[c];
            acc[2][c] += hv2 * w[c];
            acc[3][c] += hv3 * w[c];
        }
    }
    __syncthreads();
    #pragma unroll
    for (int j = 0; j < 4; j++)
        #pragma unroll
        for (int c = 0; c < 16; c++)
            hs[(32 * j + tx) * HP + c0 + c] = gate * acc[j][c];
    __syncthreads();

    {
        int validf = (n - row0 < MLP_ROWS ? (n - row0 > 0 ? n - row0 : 0) : MLP_ROWS) * CH;
        float* dst = out + (size_t)row0 * CH;
        for (int i = tid; i < MLP_ROWS * CH; i += 128) {
            if (i < validf) {
                int r = i >> 6, c = i & 63;
                dst[i] = hs[r * HP + c];
            }
        }
    }

    if (blockIdx.x == 0 && tid == 0 && out_size > n * CH) out[(size_t)n * CH] = gate;
}

// ---------------------------------------------------------------------------
extern "C" void kernel_launch(void* const* d_in, const int* in_sizes, int n_in,
                              void* d_out, int out_size) {
    const float* x     = (const float*)d_in[0];
    const void*  ei    = d_in[1];
    const float* W1    = (const float*)d_in[2];
    const float* b1    = (const float*)d_in[3];
    const float* W2    = (const float*)d_in[4];
    const float* b2    = (const float*)d_in[5];
    const float* alpha = (const float*)d_in[6];
    float* out = (float*)d_out;

    int n = in_sizes[0] / CH;
    int E = in_sizes[1] / 2;

    float *agg; int *counts, *offsets, *cursor, *sorted, *partials;
    cudaGetSymbolAddress((void**)&agg,      g_agg);
    cudaGetSymbolAddress((void**)&counts,   g_counts);
    cudaGetSymbolAddress((void**)&offsets,  g_offsets);
    cudaGetSymbolAddress((void**)&cursor,   g_cursor);
    cudaGetSymbolAddress((void**)&sorted,   g_sorted_src);
    cudaGetSymbolAddress((void**)&partials, g_partials);

    probe_ei_kernel<<<1, 1>>>((const int*)ei);

    int smem = (2 * CH * CH + 2 * CH + MLP_ROWS * HP) * sizeof(float);
    cudaFuncSetAttribute(mlp_kernel, cudaFuncAttributeMaxDynamicSharedMemorySize, smem);

    bool sortable = (n <= NODES_CAP) && (E <= EDGES_CAP) && (((n + 1023) / 1024) <= 256);
    int ncap = n < NODES_CAP ? n : NODES_CAP;
    int mblocks = (ncap + MLP_ROWS - 1) / MLP_ROWS;

    if (sortable) {
        int nb = (n + 1023) / 1024;
        zero_counts_kernel<<<(n + 255) / 256, 256>>>(counts, n);
        hist_kernel<<<(E + 255) / 256, 256>>>(ei, counts, E, n);
        scan1_kernel<<<nb, 1024>>>(counts, offsets, partials, n);
        scan2_kernel<<<1, 256>>>(partials, nb);
        scan3_kernel<<<(n + 255) / 256, 256>>>(offsets, partials, cursor, n);
        fill_kernel<<<(E + 255) / 256, 256>>>(ei, cursor, sorted, E, n);
        mlp_kernel<<<mblocks, 128, smem>>>(x, x, offsets, counts, sorted,
                                           W1, b1, W2, b2, alpha, out, n, out_size, 1);
    } else {
        int n4 = ncap * (CH / 4);
        init_agg_kernel<<<(n4 + 255) / 256, 256>>>((const float4*)x, (float4*)agg, n4);
        long long thr = (long long)E * 4;
        scatter_kernel<<<(int)((thr + 255) / 256), 256>>>(x, ei, agg, E, ncap);
        mlp_kernel<<<mblocks, 128, smem>>>(x, agg, offsets, counts, sorted,
                                           W1, b1, W2, b2, alpha, out, ncap, out_size, 0);
    }
}